// round 2
// baseline (speedup 1.0000x reference)
#include <cuda_runtime.h>
#include <math.h>

#define D      2048
#define NS     8
#define BSZ    16384
#define TWOD   (2*D)

// output layout: read [B,D] | attn [B,8] | alpha [1] | new_state [8,D] | new_fast [8,D]
#define OFF_READ   0
#define OFF_ATTN   ((size_t)BSZ * D)
#define OFF_ALPHA  (OFF_ATTN + (size_t)BSZ * NS)
#define OFF_NS     (OFF_ALPHA + 1)
#define OFF_NF     (OFF_NS + (size_t)NS * D)

// ---------------- device scratch (static, no allocs) ----------------
__device__ float g_S[NS * D];      // state + fast
__device__ float g_Keq[NS * D];    // keys @ Wr
__device__ float g_cq[NS];         // keys @ br
__device__ float g_sWc[NS];        // S @ Wc[0, D:2D]
__device__ float g_M1[NS * D];     // attn.T @ (h + nm)
__device__ float g_G[NS * NS];     // attn.T @ attn
__device__ float g_asum[NS];       // sum_b attn
__device__ float g_sadd;           // sum_b sigmoid(ctrl0)
__device__ float g_R2[NS * D];     // G @ S
__device__ float g_delta[NS * D];  // partial delta (first two terms)

// ---------------- prep1: S = state + fast ; zero accumulators ----------------
__global__ void k_prep1(const float* __restrict__ state, const float* __restrict__ fast) {
    int i = blockIdx.x * blockDim.x + threadIdx.x;   // 0..16383
    g_S[i]     = state[i] + fast[i];
    g_Keq[i]   = 0.f;
    g_M1[i]    = 0.f;
    g_delta[i] = 0.f;
    if (i < NS * NS) g_G[i] = 0.f;
    if (i < NS)      g_asum[i] = 0.f;
    if (i == 0)      g_sadd = 0.f;
}

// ---------------- keq: Keq[s,i] = sum_j keys[s,j] * Wr[j,i] ----------------
// grid (8 i-chunks of 256, 16 j-chunks of 128), 256 threads.
__global__ void k_keq(const float* __restrict__ keys, const float* __restrict__ Wr) {
    __shared__ float ks[NS][128];
    int t = threadIdx.x;
    int j0 = blockIdx.y * 128;
    int i  = blockIdx.x * 256 + t;
    for (int idx = t; idx < NS * 128; idx += 256)
        ks[idx >> 7][idx & 127] = keys[(idx >> 7) * D + j0 + (idx & 127)];
    __syncthreads();
    float acc[NS];
#pragma unroll
    for (int s = 0; s < NS; s++) acc[s] = 0.f;
    for (int jj = 0; jj < 128; jj++) {
        float w = Wr[(size_t)(j0 + jj) * D + i];
#pragma unroll
        for (int s = 0; s < NS; s++) acc[s] += ks[s][jj] * w;
    }
#pragma unroll
    for (int s = 0; s < NS; s++) atomicAdd(&g_Keq[s * D + i], acc[s]);
}

// ---------------- prep2: cq[s] = keys[s].br ; sWc[s] = S[s].Wc[0,D:] ----------------
__global__ void k_prep2(const float* __restrict__ keys, const float* __restrict__ br,
                        const float* __restrict__ Wc) {
    __shared__ float rbuf[8];
    int s = blockIdx.x >> 1;
    int which = blockIdx.x & 1;
    const float* a = which ? (g_S + s * D) : (keys + s * D);
    const float* w = which ? (Wc + D) : br;
    float acc = 0.f;
    for (int i = threadIdx.x; i < D; i += 256) acc += a[i] * w[i];
#pragma unroll
    for (int off = 16; off; off >>= 1) acc += __shfl_xor_sync(0xffffffffu, acc, off);
    if ((threadIdx.x & 31) == 0) rbuf[threadIdx.x >> 5] = acc;
    __syncthreads();
    if (threadIdx.x == 0) {
        float tot = 0.f;
#pragma unroll
        for (int k = 0; k < 8; k++) tot += rbuf[k];
        if (which) g_sWc[s] = tot; else g_cq[s] = tot;
    }
}

// ---------------- fused per-row kernel (4 rows per iteration) ----------------
// Per row b: logits = h.Keq^T + cq ; softmax -> attn (write out);
// read = attn @ S (write out); ctrl0 -> sigmoid sum; M1 += attn^T (h+nm);
// G += attn attn^T ; asum += attn.
__global__ __launch_bounds__(512, 2)
void k_fused(const float* __restrict__ h, const float* __restrict__ nm,
             const float* __restrict__ Wc, const float* __restrict__ bc,
             float* __restrict__ attn_out, float* __restrict__ read_out) {
    __shared__ float red[16][4][9];
    __shared__ float attn_sm[4][8];
    __shared__ float swc_sm[8];
    __shared__ float cq_sm[8];
    int t = threadIdx.x;
    int lane = t & 31, warp = t >> 5;
    if (t < 8) { swc_sm[t] = g_sWc[t]; cq_sm[t] = g_cq[t]; }

    // per-thread persistent state: my 4 columns (4*t .. 4*t+3)
    float keq[NS][4];
    float sl[NS][4];
#pragma unroll
    for (int s = 0; s < NS; s++) {
        float4 v = ((const float4*)(g_Keq + s * D))[t];
        keq[s][0] = v.x; keq[s][1] = v.y; keq[s][2] = v.z; keq[s][3] = v.w;
        float4 u = ((const float4*)(g_S + s * D))[t];
        sl[s][0] = u.x; sl[s][1] = u.y; sl[s][2] = u.z; sl[s][3] = u.w;
    }
    float4 wv = ((const float4*)Wc)[t];   // Wc[0, 4t..4t+3]
    float bc0 = bc[0];

    float m1[NS][4];
#pragma unroll
    for (int s = 0; s < NS; s++) { m1[s][0]=0.f; m1[s][1]=0.f; m1[s][2]=0.f; m1[s][3]=0.f; }
    float gl = 0.f, asl = 0.f, saddl = 0.f;
    bool hi16 = (lane & 16) != 0;
    bool hi8  = (lane & 8) != 0;
    __syncthreads();

    for (int batch = blockIdx.x; batch < BSZ / 4; batch += gridDim.x) {
        int b = batch * 4;
        float4 h4[4], n4[4];
#pragma unroll
        for (int r = 0; r < 4; r++) {
            h4[r] = ((const float4*)(h  + (size_t)(b + r) * D))[t];
            n4[r] = ((const float4*)(nm + (size_t)(b + r) * D))[t];
        }
        // 9 partial dots per row: 8 slot logits + Wc0 dot
        float p[36];
#pragma unroll
        for (int r = 0; r < 4; r++) {
#pragma unroll
            for (int s = 0; s < NS; s++)
                p[r*9+s] = keq[s][0]*h4[r].x + keq[s][1]*h4[r].y
                         + keq[s][2]*h4[r].z + keq[s][3]*h4[r].w;
            p[r*9+8] = wv.x*h4[r].x + wv.y*h4[r].y + wv.z*h4[r].z + wv.w*h4[r].w;
        }
        // split-exchange reduce: level 0 (xor16) splits rows {0,1}|{2,3}
#pragma unroll
        for (int k = 0; k < 18; k++) {
            float other = hi16 ? p[k] : p[18 + k];
            float got = __shfl_xor_sync(0xffffffffu, other, 16);
            float keep = hi16 ? p[18 + k] : p[k];
            p[k] = keep + got;
        }
        // level 1 (xor8) splits remaining two rows
#pragma unroll
        for (int k = 0; k < 9; k++) {
            float other = hi8 ? p[k] : p[9 + k];
            float got = __shfl_xor_sync(0xffffffffu, other, 8);
            float keep = hi8 ? p[9 + k] : p[k];
            p[k] = keep + got;
        }
        // now 8-lane group g = lane>>3 owns row g; butterfly within group
#pragma unroll
        for (int d = 4; d; d >>= 1) {
#pragma unroll
            for (int k = 0; k < 9; k++)
                p[k] += __shfl_xor_sync(0xffffffffu, p[k], d);
        }
        {
            int g = lane >> 3, ll = lane & 7;
            red[warp][g][ll] = p[ll];
            if (ll == 0) red[warp][g][8] = p[8];
        }
        __syncthreads();
        if (warp < 4) {   // warp r does softmax for row b+r
            float v = 0.f;
            if (lane < 9) {
#pragma unroll
                for (int w = 0; w < 16; w++) v += red[w][warp][lane];
            }
            float hcv = __shfl_sync(0xffffffffu, v, 8);
            float logit = (lane < 8) ? (v + cq_sm[lane]) : -1e30f;
            float m = logit;
#pragma unroll
            for (int d = 1; d < 8; d <<= 1) m = fmaxf(m, __shfl_xor_sync(0xffffffffu, m, d));
            float e = (lane < 8) ? expf(logit - m) : 0.f;
            float se = e;
#pragma unroll
            for (int d = 1; d < 8; d <<= 1) se += __shfl_xor_sync(0xffffffffu, se, d);
            float a = e / se;
            float aw = (lane < 8) ? a * swc_sm[lane] : 0.f;
#pragma unroll
            for (int d = 1; d < 8; d <<= 1) aw += __shfl_xor_sync(0xffffffffu, aw, d);
            if (lane < 8) {
                attn_sm[warp][lane] = a;
                attn_out[(size_t)(b + warp) * NS + lane] = a;
                asl += a;
            }
            if (lane == 0) {
                float ctrl0 = hcv + aw + bc0;
                saddl += 1.f / (1.f + expf(-ctrl0));
            }
        }
        __syncthreads();
        // M1 accumulation + read output for the 4 rows
#pragma unroll
        for (int r = 0; r < 4; r++) {
            float hn0 = h4[r].x + n4[r].x, hn1 = h4[r].y + n4[r].y;
            float hn2 = h4[r].z + n4[r].z, hn3 = h4[r].w + n4[r].w;
            float4 rd = {0.f, 0.f, 0.f, 0.f};
#pragma unroll
            for (int s = 0; s < NS; s++) {
                float as = attn_sm[r][s];
                m1[s][0] += as * hn0; m1[s][1] += as * hn1;
                m1[s][2] += as * hn2; m1[s][3] += as * hn3;
                rd.x += as * sl[s][0]; rd.y += as * sl[s][1];
                rd.z += as * sl[s][2]; rd.w += as * sl[s][3];
            }
            ((float4*)(read_out + (size_t)(b + r) * D))[t] = rd;
        }
        if (t < 64) {
#pragma unroll
            for (int r = 0; r < 4; r++)
                gl += attn_sm[r][t >> 3] * attn_sm[r][t & 7];
        }
        // attn_sm/red hazards separated by the two __syncthreads above
    }
    __syncthreads();
#pragma unroll
    for (int s = 0; s < NS; s++) {
#pragma unroll
        for (int k = 0; k < 4; k++)
            atomicAdd(&g_M1[s * D + 4 * t + k], m1[s][k]);
    }
    if (t < 64) atomicAdd(&g_G[t], gl);
    if (warp < 4 && lane < 8) atomicAdd(&g_asum[lane], asl);
    if (warp < 4 && lane == 0) atomicAdd(&g_sadd, saddl);
}

// ---------------- R2 = G @ S ----------------
__global__ void k_r2() {
    int idx = blockIdx.x * 256 + threadIdx.x;  // 16384
    int s = idx >> 11, i = idx & (D - 1);
    float acc = 0.f;
#pragma unroll
    for (int sp = 0; sp < NS; sp++) acc += g_G[s * NS + sp] * g_S[sp * D + i];
    g_R2[idx] = acc;
}

// ---------------- delta partials: [M1 | R2] @ Ww^T ----------------
// grid (8 o-chunks of 256, 16 i-chunks of 256), 256 threads (one o each)
__global__ __launch_bounds__(256)
void k_delta(const float* __restrict__ Ww) {
    __shared__ float u_sm[NS][256];
    int t = threadIdx.x;
    int i0 = blockIdx.y * 256;                  // 0..4095
    const float* U = (i0 < D) ? g_M1 : g_R2;
    int ui0 = i0 & (D - 1);
    for (int idx = t; idx < NS * 256; idx += 256)
        u_sm[idx >> 8][idx & 255] = U[(idx >> 8) * D + ui0 + (idx & 255)];
    __syncthreads();
    int o = blockIdx.x * 256 + t;
    float acc[NS];
#pragma unroll
    for (int s = 0; s < NS; s++) acc[s] = 0.f;
    const float* wrow = Ww + (size_t)o * TWOD + i0;
    for (int ii = 0; ii < 256; ii += 4) {
        float4 w = *(const float4*)(wrow + ii);
#pragma unroll
        for (int s = 0; s < NS; s++)
            acc[s] += u_sm[s][ii]*w.x + u_sm[s][ii+1]*w.y + u_sm[s][ii+2]*w.z + u_sm[s][ii+3]*w.w;
    }
#pragma unroll
    for (int s = 0; s < NS; s++) atomicAdd(&g_delta[s * D + o], acc[s]);
}

// ---------------- final: alpha, new_state, new_fast ----------------
__global__ void k_final(const float* __restrict__ bw, const float* __restrict__ state,
                        const float* __restrict__ fast, float* __restrict__ out) {
    int idx = blockIdx.x * 256 + threadIdx.x;   // 16384
    float mean = g_sadd * (1.f / (float)BSZ);
    float alpha = 0.02f + 0.98f * mean;
    alpha = fminf(fmaxf(alpha, 0.f), 1.f);      // ALPHA_BOOST = 1
    int s = idx >> 11, o = idx & (D - 1);
    float delta = g_delta[idx] + g_asum[s] * bw[o];
    out[OFF_NS + idx] = (1.f - alpha) * state[idx] + alpha * delta;
    out[OFF_NF + idx] = 0.95f * fast[idx] + 0.05f * delta;
    if (idx == 0) out[OFF_ALPHA] = alpha;
}

// ---------------- launch ----------------
extern "C" void kernel_launch(void* const* d_in, const int* in_sizes, int n_in,
                              void* d_out, int out_size) {
    const float* h     = (const float*)d_in[0];
    const float* nm    = (const float*)d_in[1];
    const float* keys  = (const float*)d_in[2];
    const float* Wr    = (const float*)d_in[3];
    const float* br    = (const float*)d_in[4];
    const float* Wc    = (const float*)d_in[5];
    const float* bc    = (const float*)d_in[6];
    const float* Ww    = (const float*)d_in[7];
    const float* bw    = (const float*)d_in[8];
    const float* state = (const float*)d_in[9];
    const float* fast  = (const float*)d_in[10];
    float* out = (float*)d_out;

    k_prep1<<<64, 256>>>(state, fast);
    k_keq<<<dim3(8, 16), 256>>>(keys, Wr);
    k_prep2<<<16, 256>>>(keys, br, Wc);
    k_fused<<<296, 512>>>(h, nm, Wc, bc, out + OFF_ATTN, out + OFF_READ);
    k_r2<<<64, 256>>>();
    k_delta<<<dim3(8, 16), 256>>>(Ww);
    k_final<<<64, 256>>>(bw, state, fast, out);
}

// round 3
// speedup vs baseline: 1.7130x; 1.7130x over previous
#include <cuda_runtime.h>
#include <math.h>

#define D      2048
#define NS     8
#define BSZ    16384
#define TWOD   (2*D)

// output layout: read [B,D] | attn [B,8] | alpha [1] | new_state [8,D] | new_fast [8,D]
#define OFF_READ   0
#define OFF_ATTN   ((size_t)BSZ * D)
#define OFF_ALPHA  (OFF_ATTN + (size_t)BSZ * NS)
#define OFF_NS     (OFF_ALPHA + 1)
#define OFF_NF     (OFF_NS + (size_t)NS * D)

// ---------------- device scratch (static, no allocs) ----------------
__device__ float g_S[NS * D];      // state + fast
__device__ float g_Keq[NS * D];    // keys @ Wr
__device__ float g_cq[NS];         // keys @ br
__device__ float g_sWc[NS];        // S @ Wc[0, D:2D]
__device__ float g_M1[NS * D];     // attn.T @ (h + nm)
__device__ float g_G[NS * NS];     // attn.T @ attn
__device__ float g_asum[NS];       // sum_b attn
__device__ float g_sadd;           // sum_b sigmoid(ctrl0)
__device__ float g_R2[NS * D];     // G @ S
__device__ float g_delta[NS * D];  // partial delta (first two terms)

// ---------------- prep1: S = state + fast ; zero accumulators ----------------
__global__ void k_prep1(const float* __restrict__ state, const float* __restrict__ fast) {
    int i = blockIdx.x * blockDim.x + threadIdx.x;   // 0..16383
    g_S[i]     = state[i] + fast[i];
    g_Keq[i]   = 0.f;
    g_M1[i]    = 0.f;
    g_delta[i] = 0.f;
    if (i < NS * NS) g_G[i] = 0.f;
    if (i < NS)      g_asum[i] = 0.f;
    if (i == 0)      g_sadd = 0.f;
}

// ---------------- keq: Keq[s,i] = sum_j keys[s,j] * Wr[j,i] ----------------
__global__ void k_keq(const float* __restrict__ keys, const float* __restrict__ Wr) {
    __shared__ float ks[NS][128];
    int t = threadIdx.x;
    int j0 = blockIdx.y * 128;
    int i  = blockIdx.x * 256 + t;
    for (int idx = t; idx < NS * 128; idx += 256)
        ks[idx >> 7][idx & 127] = keys[(idx >> 7) * D + j0 + (idx & 127)];
    __syncthreads();
    float acc[NS];
#pragma unroll
    for (int s = 0; s < NS; s++) acc[s] = 0.f;
    for (int jj = 0; jj < 128; jj++) {
        float w = Wr[(size_t)(j0 + jj) * D + i];
#pragma unroll
        for (int s = 0; s < NS; s++) acc[s] += ks[s][jj] * w;
    }
#pragma unroll
    for (int s = 0; s < NS; s++) atomicAdd(&g_Keq[s * D + i], acc[s]);
}

// ---------------- prep2: cq[s] = keys[s].br ; sWc[s] = S[s].Wc[0,D:] ----------------
__global__ void k_prep2(const float* __restrict__ keys, const float* __restrict__ br,
                        const float* __restrict__ Wc) {
    __shared__ float rbuf[8];
    int s = blockIdx.x >> 1;
    int which = blockIdx.x & 1;
    const float* a = which ? (g_S + s * D) : (keys + s * D);
    const float* w = which ? (Wc + D) : br;
    float acc = 0.f;
    for (int i = threadIdx.x; i < D; i += 256) acc += a[i] * w[i];
#pragma unroll
    for (int off = 16; off; off >>= 1) acc += __shfl_xor_sync(0xffffffffu, acc, off);
    if ((threadIdx.x & 31) == 0) rbuf[threadIdx.x >> 5] = acc;
    __syncthreads();
    if (threadIdx.x == 0) {
        float tot = 0.f;
#pragma unroll
        for (int k = 0; k < 8; k++) tot += rbuf[k];
        if (which) g_sWc[s] = tot; else g_cq[s] = tot;
    }
}

// ---------------- fused per-row kernel (4 rows / iteration, S in smem) ----------------
__global__ __launch_bounds__(512)
void k_fused(const float* __restrict__ h, const float* __restrict__ nm,
             const float* __restrict__ Wc, const float* __restrict__ bc,
             float* __restrict__ attn_out, float* __restrict__ read_out) {
    extern __shared__ float4 s_sm[];        // [NS][512]: S[s][4t..4t+3]
    __shared__ float red[16][4][9];
    __shared__ float attn_sm[4][8];
    __shared__ float swc_sm[8];
    __shared__ float cq_sm[8];
    int t = threadIdx.x;
    int lane = t & 31, warp = t >> 5;
    if (t < 8) { swc_sm[t] = g_sWc[t]; cq_sm[t] = g_cq[t]; }

    // persistent per-thread: keq (regs), S (smem), m1 accumulators (regs)
    float keq[NS][4];
#pragma unroll
    for (int s = 0; s < NS; s++) {
        float4 v = ((const float4*)(g_Keq + s * D))[t];
        keq[s][0] = v.x; keq[s][1] = v.y; keq[s][2] = v.z; keq[s][3] = v.w;
        s_sm[s * 512 + t] = ((const float4*)(g_S + s * D))[t];
    }
    float4 wv = ((const float4*)Wc)[t];   // Wc[0, 4t..4t+3]
    float bc0 = bc[0];

    float m1[NS][4];
#pragma unroll
    for (int s = 0; s < NS; s++) { m1[s][0]=0.f; m1[s][1]=0.f; m1[s][2]=0.f; m1[s][3]=0.f; }
    float gl = 0.f, asl = 0.f, saddl = 0.f;
    bool hi16 = (lane & 16) != 0;
    __syncthreads();

    for (int batch = blockIdx.x; batch < BSZ / 4; batch += gridDim.x) {
        int b = batch * 4;
        float4 hh[4];
#pragma unroll
        for (int r = 0; r < 4; r++)
            hh[r] = ((const float4*)(h + (size_t)(b + r) * D))[t];

        // dot phase: rows processed in pairs with split-exchange reduce
#pragma unroll
        for (int pr = 0; pr < 2; pr++) {
            float pa[9], pb[9];
            float4 ha = hh[2 * pr], hb = hh[2 * pr + 1];
#pragma unroll
            for (int s = 0; s < NS; s++) {
                pa[s] = keq[s][0]*ha.x + keq[s][1]*ha.y + keq[s][2]*ha.z + keq[s][3]*ha.w;
                pb[s] = keq[s][0]*hb.x + keq[s][1]*hb.y + keq[s][2]*hb.z + keq[s][3]*hb.w;
            }
            pa[8] = wv.x*ha.x + wv.y*ha.y + wv.z*ha.z + wv.w*ha.w;
            pb[8] = wv.x*hb.x + wv.y*hb.y + wv.z*hb.z + wv.w*hb.w;
            float mg[9];
#pragma unroll
            for (int k = 0; k < 9; k++) {
                float send = hi16 ? pa[k] : pb[k];
                float got  = __shfl_xor_sync(0xffffffffu, send, 16);
                float keep = hi16 ? pb[k] : pa[k];
                mg[k] = keep + got;   // lo lanes: row a, hi lanes: row b
            }
#pragma unroll
            for (int d = 8; d; d >>= 1) {
#pragma unroll
                for (int k = 0; k < 9; k++)
                    mg[k] += __shfl_xor_sync(0xffffffffu, mg[k], d);
            }
            if (lane == 0) {
#pragma unroll
                for (int k = 0; k < 9; k++) red[warp][2 * pr][k] = mg[k];
            } else if (lane == 16) {
#pragma unroll
                for (int k = 0; k < 9; k++) red[warp][2 * pr + 1][k] = mg[k];
            }
        }
        // prefetch nm rows (latency hides behind sync + softmax)
        float4 nn[4];
#pragma unroll
        for (int r = 0; r < 4; r++)
            nn[r] = ((const float4*)(nm + (size_t)(b + r) * D))[t];

        __syncthreads();
        if (warp < 4) {   // warp r: softmax for row b+r
            float v = 0.f;
            if (lane < 9) {
#pragma unroll
                for (int w = 0; w < 16; w++) v += red[w][warp][lane];
            }
            float hcv = __shfl_sync(0xffffffffu, v, 8);
            float logit = (lane < 8) ? (v + cq_sm[lane]) : -1e30f;
            float m = logit;
#pragma unroll
            for (int d = 1; d < 8; d <<= 1) m = fmaxf(m, __shfl_xor_sync(0xffffffffu, m, d));
            float e = (lane < 8) ? expf(logit - m) : 0.f;
            float se = e;
#pragma unroll
            for (int d = 1; d < 8; d <<= 1) se += __shfl_xor_sync(0xffffffffu, se, d);
            float a = e / se;
            float aw = (lane < 8) ? a * swc_sm[lane] : 0.f;
#pragma unroll
            for (int d = 1; d < 8; d <<= 1) aw += __shfl_xor_sync(0xffffffffu, aw, d);
            if (lane < 8) {
                attn_sm[warp][lane] = a;
                attn_out[(size_t)(b + warp) * NS + lane] = a;
                asl += a;
            }
            if (lane == 0) {
                float ctrl0 = hcv + aw + bc0;
                saddl += 1.f / (1.f + expf(-ctrl0));
            }
        }
        __syncthreads();
        // phase 2: M1 accumulation + fused read output
#pragma unroll
        for (int r = 0; r < 4; r++) {
            float hn0 = hh[r].x + nn[r].x, hn1 = hh[r].y + nn[r].y;
            float hn2 = hh[r].z + nn[r].z, hn3 = hh[r].w + nn[r].w;
            float4 rd = {0.f, 0.f, 0.f, 0.f};
#pragma unroll
            for (int s = 0; s < NS; s++) {
                float as = attn_sm[r][s];
                m1[s][0] += as * hn0; m1[s][1] += as * hn1;
                m1[s][2] += as * hn2; m1[s][3] += as * hn3;
                float4 sv = s_sm[s * 512 + t];
                rd.x += as * sv.x; rd.y += as * sv.y;
                rd.z += as * sv.z; rd.w += as * sv.w;
            }
            ((float4*)(read_out + (size_t)(b + r) * D))[t] = rd;
        }
        if (t < 64) {
#pragma unroll
            for (int r = 0; r < 4; r++)
                gl += attn_sm[r][t >> 3] * attn_sm[r][t & 7];
        }
        // next batch's red write is fenced from this softmax's red reads by
        // the sync above; attn_sm next write is fenced by next batch's sync1
    }
    __syncthreads();
#pragma unroll
    for (int s = 0; s < NS; s++) {
#pragma unroll
        for (int k = 0; k < 4; k++)
            atomicAdd(&g_M1[s * D + 4 * t + k], m1[s][k]);
    }
    if (t < 64) atomicAdd(&g_G[t], gl);
    if (warp < 4 && lane < 8) atomicAdd(&g_asum[lane], asl);
    if (warp < 4 && lane == 0) atomicAdd(&g_sadd, saddl);
}

// ---------------- R2 = G @ S ----------------
__global__ void k_r2() {
    int idx = blockIdx.x * 256 + threadIdx.x;  // 16384
    int s = idx >> 11, i = idx & (D - 1);
    float acc = 0.f;
#pragma unroll
    for (int sp = 0; sp < NS; sp++) acc += g_G[s * NS + sp] * g_S[sp * D + i];
    g_R2[idx] = acc;
}

// ---------------- delta partials: [M1 | R2] @ Ww^T ----------------
__global__ __launch_bounds__(256)
void k_delta(const float* __restrict__ Ww) {
    __shared__ float u_sm[NS][256];
    int t = threadIdx.x;
    int i0 = blockIdx.y * 256;                  // 0..4095
    const float* U = (i0 < D) ? g_M1 : g_R2;
    int ui0 = i0 & (D - 1);
    for (int idx = t; idx < NS * 256; idx += 256)
        u_sm[idx >> 8][idx & 255] = U[(idx >> 8) * D + ui0 + (idx & 255)];
    __syncthreads();
    int o = blockIdx.x * 256 + t;
    float acc[NS];
#pragma unroll
    for (int s = 0; s < NS; s++) acc[s] = 0.f;
    const float* wrow = Ww + (size_t)o * TWOD + i0;
    for (int ii = 0; ii < 256; ii += 4) {
        float4 w = *(const float4*)(wrow + ii);
#pragma unroll
        for (int s = 0; s < NS; s++)
            acc[s] += u_sm[s][ii]*w.x + u_sm[s][ii+1]*w.y + u_sm[s][ii+2]*w.z + u_sm[s][ii+3]*w.w;
    }
#pragma unroll
    for (int s = 0; s < NS; s++) atomicAdd(&g_delta[s * D + o], acc[s]);
}

// ---------------- final: alpha, new_state, new_fast ----------------
__global__ void k_final(const float* __restrict__ bw, const float* __restrict__ state,
                        const float* __restrict__ fast, float* __restrict__ out) {
    int idx = blockIdx.x * 256 + threadIdx.x;   // 16384
    float mean = g_sadd * (1.f / (float)BSZ);
    float alpha = 0.02f + 0.98f * mean;
    alpha = fminf(fmaxf(alpha, 0.f), 1.f);      // ALPHA_BOOST = 1
    int s = idx >> 11, o = idx & (D - 1);
    float delta = g_delta[idx] + g_asum[s] * bw[o];
    out[OFF_NS + idx] = (1.f - alpha) * state[idx] + alpha * delta;
    out[OFF_NF + idx] = 0.95f * fast[idx] + 0.05f * delta;
    if (idx == 0) out[OFF_ALPHA] = alpha;
}

// ---------------- launch ----------------
extern "C" void kernel_launch(void* const* d_in, const int* in_sizes, int n_in,
                              void* d_out, int out_size) {
    const float* h     = (const float*)d_in[0];
    const float* nm    = (const float*)d_in[1];
    const float* keys  = (const float*)d_in[2];
    const float* Wr    = (const float*)d_in[3];
    const float* br    = (const float*)d_in[4];
    const float* Wc    = (const float*)d_in[5];
    const float* bc    = (const float*)d_in[6];
    const float* Ww    = (const float*)d_in[7];
    const float* bw    = (const float*)d_in[8];
    const float* state = (const float*)d_in[9];
    const float* fast  = (const float*)d_in[10];
    float* out = (float*)d_out;

    const int SMEM_DYN = NS * 512 * sizeof(float4);   // 64KB for S tile
    cudaFuncSetAttribute(k_fused, cudaFuncAttributeMaxDynamicSharedMemorySize, SMEM_DYN);

    k_prep1<<<64, 256>>>(state, fast);
    k_keq<<<dim3(8, 16), 256>>>(keys, Wr);
    k_prep2<<<16, 256>>>(keys, br, Wc);
    k_fused<<<148, 512, SMEM_DYN>>>(h, nm, Wc, bc, out + OFF_ATTN, out + OFF_READ);
    k_r2<<<64, 256>>>();
    k_delta<<<dim3(8, 16), 256>>>(Ww);
    k_final<<<64, 256>>>(bw, state, fast, out);
}